// round 3
// baseline (speedup 1.0000x reference)
#include <cuda_runtime.h>
#include <cuda_fp16.h>
#include <mma.h>

using namespace nvcuda;

#define M_DIM 8192
#define N_DIM 4096
#define K_DIM 4096
#define N_CODES (N_DIM * K_DIM / 8)   // 2,097,152
#define X_ELEMS (M_DIM * K_DIM)       // 33,554,432

constexpr int BM = 128;
constexpr int BN = 128;
constexpr int BK = 32;
constexpr int LDS = BK + 8;

__device__ __align__(16) __half g_W[(size_t)N_DIM * K_DIM];   // 32 MB
__device__ __align__(16) __half g_X[(size_t)M_DIM * K_DIM];   // 64 MB
__device__ int g_idx_is64;    // 1 if indices are int64
__device__ int g_cb_mode;     // 0=fp16, 1=bf16, 2=fp32

// ---------------------------------------------------------------------------
// Probe: detect indices width (int32 vs int64) and codebook wire dtype.
// Codebook holds 2048 values ~N(0,1). Read first 2048 halfwords as fp16:
//   fp32 misread -> low halves of fp32 bits are ~uniform -> Inf/NaN & huge
//                   values guaranteed among 1024+ samples.
//   bf16 misread -> nearly all values land in [0.5, 4) magnitude.
//   true fp16    -> ~38% of values have |v| < 0.5, none huge.
// ---------------------------------------------------------------------------
__global__ void probe_kernel(const unsigned long long* __restrict__ idx64,
                             const unsigned short* __restrict__ cb_raw) {
    const int lane = threadIdx.x;  // 32 threads

    // --- indices ---
    unsigned long long hi = (lane < 16) ? (idx64[lane] >> 32) : 0ULL;
    int any_hi = __any_sync(0xFFFFFFFFu, hi != 0ULL);

    // --- codebook ---
    int big = 0, small = 0;
    for (int j = 0; j < 64; j++) {
        unsigned short u = cb_raw[lane * 64 + j];
        int expf = (u >> 10) & 0x1F;
        // non-finite or |v| >= 64  <=>  exponent field >= 21
        if (expf >= 21) big++;
        // |v| < 0.5  <=>  exponent field <= 13 (covers subnormals/zero too)
        if (expf <= 13) small++;
    }
#pragma unroll
    for (int off = 16; off > 0; off >>= 1) {
        big   += __shfl_xor_sync(0xFFFFFFFFu, big, off);
        small += __shfl_xor_sync(0xFFFFFFFFu, small, off);
    }

    if (lane == 0) {
        g_idx_is64 = any_hi ? 0 : 1;
        g_cb_mode = (big > 0) ? 2 : ((small > 300) ? 0 : 1);
    }
}

// ---------------------------------------------------------------------------
// Gather-dequant -> g_W (fp16). Handles fp16/bf16/fp32 codebook.
// ---------------------------------------------------------------------------
__global__ void dequant_kernel(const void* __restrict__ indices,
                               const void* __restrict__ codebook) {
    int i = blockIdx.x * blockDim.x + threadIdx.x;
    if (i >= N_CODES) return;

    long long code;
    if (g_idx_is64) code = reinterpret_cast<const long long*>(indices)[i];
    else            code = reinterpret_cast<const int*>(indices)[i];
    code &= 255;  // safety: valid range [0,256)

    const int mode = g_cb_mode;
    uint4 v;
    if (mode == 0) {
        // fp16: row = 16 bytes
        v = __ldg(reinterpret_cast<const uint4*>(codebook) + code);
    } else if (mode == 2) {
        // fp32: row = 32 bytes -> convert to fp16 (rn)
        const float4* cb32 = reinterpret_cast<const float4*>(codebook);
        float4 a = __ldg(cb32 + 2 * code);
        float4 b = __ldg(cb32 + 2 * code + 1);
        __half2 h0 = __floats2half2_rn(a.x, a.y);
        __half2 h1 = __floats2half2_rn(a.z, a.w);
        __half2 h2 = __floats2half2_rn(b.x, b.y);
        __half2 h3 = __floats2half2_rn(b.z, b.w);
        v.x = *reinterpret_cast<unsigned*>(&h0);
        v.y = *reinterpret_cast<unsigned*>(&h1);
        v.z = *reinterpret_cast<unsigned*>(&h2);
        v.w = *reinterpret_cast<unsigned*>(&h3);
    } else {
        // bf16: row = 16 bytes of bf16 -> widen to fp32 -> fp16
        uint4 raw = __ldg(reinterpret_cast<const uint4*>(codebook) + code);
        unsigned* rw = reinterpret_cast<unsigned*>(&raw);
        unsigned* vw = reinterpret_cast<unsigned*>(&v);
#pragma unroll
        for (int w = 0; w < 4; w++) {
            unsigned lo_bits = (rw[w] & 0xFFFFu) << 16;
            unsigned hi_bits = (rw[w] & 0xFFFF0000u);
            float lo = __uint_as_float(lo_bits);
            float hi = __uint_as_float(hi_bits);
            __half2 h = __floats2half2_rn(lo, hi);
            vw[w] = *reinterpret_cast<unsigned*>(&h);
        }
    }
    reinterpret_cast<uint4*>(g_W)[i] = v;
}

// ---------------------------------------------------------------------------
// x fp32 -> fp16, 8 elements per thread
// ---------------------------------------------------------------------------
__global__ void convert_kernel(const float* __restrict__ x) {
    int i = blockIdx.x * blockDim.x + threadIdx.x;
    if (i >= X_ELEMS / 8) return;
    const float4* in4 = reinterpret_cast<const float4*>(x);
    float4 a = in4[2 * i];
    float4 b = in4[2 * i + 1];
    __half2 h0 = __floats2half2_rn(a.x, a.y);
    __half2 h1 = __floats2half2_rn(a.z, a.w);
    __half2 h2 = __floats2half2_rn(b.x, b.y);
    __half2 h3 = __floats2half2_rn(b.z, b.w);
    uint4 out;
    out.x = *reinterpret_cast<unsigned*>(&h0);
    out.y = *reinterpret_cast<unsigned*>(&h1);
    out.z = *reinterpret_cast<unsigned*>(&h2);
    out.w = *reinterpret_cast<unsigned*>(&h3);
    reinterpret_cast<uint4*>(g_X)[i] = out;
}

// ---------------------------------------------------------------------------
// GEMM out[m][n] = sum_k g_X[m][k] * g_W[n][k]  (fp16 in, fp32 acc)
// ---------------------------------------------------------------------------
__global__ __launch_bounds__(256, 2)
void gemm_kernel(float* __restrict__ out) {
    __shared__ __align__(16) __half As[2][BM][LDS];
    __shared__ __align__(16) __half Bs[2][BN][LDS];

    const int tid = threadIdx.x;
    const int bm  = blockIdx.y;
    const int bn  = blockIdx.x;

    const __half* Ag = g_X + (size_t)bm * BM * K_DIM;
    const __half* Bg = g_W + (size_t)bn * BN * K_DIM;

    const int lrow = tid >> 2;
    const int lcol = (tid & 3) * 8;

    const int warpId = tid >> 5;
    const int wm = warpId >> 2;
    const int wn = warpId & 3;

    wmma::fragment<wmma::accumulator, 16, 16, 16, float> c[4][2];
#pragma unroll
    for (int i = 0; i < 4; i++)
#pragma unroll
        for (int j = 0; j < 2; j++)
            wmma::fill_fragment(c[i][j], 0.0f);

    uint4 ra0, ra1, rb0, rb1;

    auto load_global = [&](int kt) {
        const size_t ko = (size_t)kt * BK + lcol;
        ra0 = *reinterpret_cast<const uint4*>(Ag + (size_t)lrow        * K_DIM + ko);
        ra1 = *reinterpret_cast<const uint4*>(Ag + (size_t)(lrow + 64) * K_DIM + ko);
        rb0 = *reinterpret_cast<const uint4*>(Bg + (size_t)lrow        * K_DIM + ko);
        rb1 = *reinterpret_cast<const uint4*>(Bg + (size_t)(lrow + 64) * K_DIM + ko);
    };
    auto store_shared = [&](int s) {
        *reinterpret_cast<uint4*>(&As[s][lrow     ][lcol]) = ra0;
        *reinterpret_cast<uint4*>(&As[s][lrow + 64][lcol]) = ra1;
        *reinterpret_cast<uint4*>(&Bs[s][lrow     ][lcol]) = rb0;
        *reinterpret_cast<uint4*>(&Bs[s][lrow + 64][lcol]) = rb1;
    };

    load_global(0);
    store_shared(0);
    __syncthreads();

    const int NT = K_DIM / BK;
    for (int kt = 0; kt < NT; kt++) {
        const int s = kt & 1;
        if (kt + 1 < NT) load_global(kt + 1);

#pragma unroll
        for (int kk = 0; kk < BK / 16; kk++) {
            wmma::fragment<wmma::matrix_a, 16, 16, 16, __half, wmma::row_major> af[4];
            wmma::fragment<wmma::matrix_b, 16, 16, 16, __half, wmma::col_major> bf[2];
#pragma unroll
            for (int i = 0; i < 4; i++)
                wmma::load_matrix_sync(af[i], &As[s][wm * 64 + i * 16][kk * 16], LDS);
#pragma unroll
            for (int j = 0; j < 2; j++)
                wmma::load_matrix_sync(bf[j], &Bs[s][wn * 32 + j * 16][kk * 16], LDS);
#pragma unroll
            for (int i = 0; i < 4; i++)
#pragma unroll
                for (int j = 0; j < 2; j++)
                    wmma::mma_sync(c[i][j], af[i], bf[j], c[i][j]);
        }

        if (kt + 1 < NT) {
            __syncthreads();
            store_shared(s ^ 1);
            __syncthreads();
        }
    }

    const int m0 = bm * BM + wm * 64;
    const int n0 = bn * BN + wn * 32;
#pragma unroll
    for (int i = 0; i < 4; i++)
#pragma unroll
        for (int j = 0; j < 2; j++)
            wmma::store_matrix_sync(out + (size_t)(m0 + i * 16) * N_DIM + (n0 + j * 16),
                                    c[i][j], N_DIM, wmma::mem_row_major);
}

// ---------------------------------------------------------------------------
// Entry. Inputs identified by element count:
//   x: 33,554,432 | codebook: 2,048 | indices: 2,097,152
// ---------------------------------------------------------------------------
extern "C" void kernel_launch(void* const* d_in, const int* in_sizes, int n_in,
                              void* d_out, int out_size) {
    const float* x        = nullptr;
    const void*  codebook = nullptr;
    const void*  indices  = nullptr;

    for (int i = 0; i < n_in; i++) {
        if      (in_sizes[i] == X_ELEMS)  x        = (const float*)d_in[i];
        else if (in_sizes[i] == 2048)     codebook = d_in[i];
        else if (in_sizes[i] == N_CODES)  indices  = d_in[i];
    }
    float* out = (float*)d_out;
    (void)out_size;

    probe_kernel<<<1, 32>>>((const unsigned long long*)indices,
                            (const unsigned short*)codebook);
    dequant_kernel<<<(N_CODES + 255) / 256, 256>>>(indices, codebook);
    convert_kernel<<<(X_ELEMS / 8 + 255) / 256, 256>>>(x);

    dim3 grid(N_DIM / BN, M_DIM / BM);
    gemm_kernel<<<grid, 256>>>(out);
}